// round 5
// baseline (speedup 1.0000x reference)
#include <cuda_runtime.h>
#include <cuda_fp16.h>

// Problem: GridSamplePScan  B=1, L=16, C=8, H=128, W=128
// out[t,c,h,w] = sum_{k<=t} bilinear(images[k,c], base(h,w) + cum[t]-cum[k])
// x wrapped periodically (mod 2 normalized), zero-padding taps.
//
// R3: fp16 NHWC image scratch -> one LDG.128 per bilinear tap (was two fp32),
//     halving L1tex wavefront pressure (the measured 79.5% bottleneck).
//     (R2 resubmit with the compile error fixed.)

#define L_ 16
#define C_ 8
#define H_ 128
#define W_ 128
#define HW_ (H_ * W_)

// NHWC fp16 images scratch: [L, H, W, C] halves = 4 MB
__device__ __half g_imgT[L_ * H_ * W_ * C_];

// ---------------------------------------------------------------------------
// Kernel 1: transpose+quantize images [L,C,H,W] fp32 -> [L,H,W,C] fp16
// ---------------------------------------------------------------------------
__global__ __launch_bounds__(256) void transpose_nhwc_kernel(const float* __restrict__ images) {
    int idx = blockIdx.x * blockDim.x + threadIdx.x;  // over L*H*W
    if (idx >= L_ * HW_) return;
    int k = idx >> 14;           // / (H*W)
    int hw = idx & (HW_ - 1);

    const float* src = images + (size_t)k * C_ * HW_ + hw;
    float v0 = src[0 * HW_];
    float v1 = src[1 * HW_];
    float v2 = src[2 * HW_];
    float v3 = src[3 * HW_];
    float v4 = src[4 * HW_];
    float v5 = src[5 * HW_];
    float v6 = src[6 * HW_];
    float v7 = src[7 * HW_];

    __half2 h0 = __floats2half2_rn(v0, v1);
    __half2 h1 = __floats2half2_rn(v2, v3);
    __half2 h2 = __floats2half2_rn(v4, v5);
    __half2 h3 = __floats2half2_rn(v6, v7);

    uint4 pack;
    pack.x = *reinterpret_cast<unsigned int*>(&h0);
    pack.y = *reinterpret_cast<unsigned int*>(&h1);
    pack.z = *reinterpret_cast<unsigned int*>(&h2);
    pack.w = *reinterpret_cast<unsigned int*>(&h3);

    *reinterpret_cast<uint4*>(g_imgT + (size_t)idx * C_) = pack;
}

// ---------------------------------------------------------------------------
// Kernel 2: fused suffix-sum flow + bilinear gather + triangular accumulation
// One thread per (t, h, w); all 8 channels in registers. fp16 taps, fp32 math.
// ---------------------------------------------------------------------------
__device__ __forceinline__ void accum_tap(const uint4 p, const float wgt,
                                          float& a0, float& a1, float& a2, float& a3,
                                          float& a4, float& a5, float& a6, float& a7) {
    __half2 h0 = *reinterpret_cast<const __half2*>(&p.x);
    __half2 h1 = *reinterpret_cast<const __half2*>(&p.y);
    __half2 h2 = *reinterpret_cast<const __half2*>(&p.z);
    __half2 h3 = *reinterpret_cast<const __half2*>(&p.w);
    float2 f0 = __half22float2(h0);
    float2 f1 = __half22float2(h1);
    float2 f2 = __half22float2(h2);
    float2 f3 = __half22float2(h3);
    a0 = fmaf(wgt, f0.x, a0);
    a1 = fmaf(wgt, f0.y, a1);
    a2 = fmaf(wgt, f1.x, a2);
    a3 = fmaf(wgt, f1.y, a3);
    a4 = fmaf(wgt, f2.x, a4);
    a5 = fmaf(wgt, f2.y, a5);
    a6 = fmaf(wgt, f3.x, a6);
    a7 = fmaf(wgt, f3.y, a7);
}

__global__ __launch_bounds__(128) void pscan_sample_kernel(const float* __restrict__ flows,
                                                           float* __restrict__ out) {
    const int w = threadIdx.x;               // 0..127
    const int h = blockIdx.x;                // 0..127
    const int t = (L_ - 1) - blockIdx.y;     // long blocks (big t) first
    const int hw = h * W_ + w;

    // base grid (pixel centers, normalized, align_corners=False)
    const float bx = (2.0f * (float)w + 1.0f) * (1.0f / (float)W_) - 1.0f;
    const float by = (2.0f * (float)h + 1.0f) * (1.0f / (float)H_) - 1.0f;

    float a0 = 0.f, a1 = 0.f, a2 = 0.f, a3 = 0.f;
    float a4 = 0.f, a5 = 0.f, a6 = 0.f, a7 = 0.f;

    // rel(t,k) = cum[t]-cum[k] via suffix sum k = t..0
    float rx = 0.0f, ry = 0.0f;

    for (int k = t; k >= 0; --k) {
        float gx = bx + rx;
        float gy = by + ry;

        // periodic wrap in x (Python remainder semantics)
        float m = fmodf(gx + 1.0f, 2.0f);
        if (m < 0.0f) m += 2.0f;
        gx = m - 1.0f;

        float ix = (gx + 1.0f) * ((float)W_ * 0.5f) - 0.5f;
        float iy = (gy + 1.0f) * ((float)H_ * 0.5f) - 0.5f;

        float x0f = floorf(ix);
        float y0f = floorf(iy);
        float wx = ix - x0f;
        float wy = iy - y0f;

        int x0 = (int)x0f;
        int y0 = (int)y0f;
        int x1 = x0 + 1;
        int y1 = y0 + 1;

        float vx0 = (x0 >= 0 && x0 < W_) ? 1.0f : 0.0f;
        float vx1 = (x1 >= 0 && x1 < W_) ? 1.0f : 0.0f;
        float vy0 = (y0 >= 0 && y0 < H_) ? 1.0f : 0.0f;
        float vy1 = (y1 >= 0 && y1 < H_) ? 1.0f : 0.0f;

        int cx0 = min(max(x0, 0), W_ - 1);
        int cx1 = min(max(x1, 0), W_ - 1);
        int cy0 = min(max(y0, 0), H_ - 1);
        int cy1 = min(max(y1, 0), H_ - 1);

        float w00 = (1.0f - wx) * (1.0f - wy) * vx0 * vy0;
        float w10 = wx * (1.0f - wy) * vx1 * vy0;
        float w01 = (1.0f - wx) * wy * vx0 * vy1;
        float w11 = wx * wy * vx1 * vy1;

        const __half* imgk = g_imgT + (size_t)k * HW_ * C_;

        // issue all 4 tap loads up front (one LDG.128 each)
        uint4 p00 = *reinterpret_cast<const uint4*>(imgk + (size_t)(cy0 * W_ + cx0) * C_);
        uint4 p10 = *reinterpret_cast<const uint4*>(imgk + (size_t)(cy0 * W_ + cx1) * C_);
        uint4 p01 = *reinterpret_cast<const uint4*>(imgk + (size_t)(cy1 * W_ + cx0) * C_);
        uint4 p11 = *reinterpret_cast<const uint4*>(imgk + (size_t)(cy1 * W_ + cx1) * C_);

        // prefetch flow for next iter early
        float fx = 0.f, fy = 0.f;
        if (k > 0) {
            fx = __ldg(flows + (size_t)(k * 2 + 0) * HW_ + hw);
            fy = __ldg(flows + (size_t)(k * 2 + 1) * HW_ + hw);
        }

        accum_tap(p00, w00, a0, a1, a2, a3, a4, a5, a6, a7);
        accum_tap(p10, w10, a0, a1, a2, a3, a4, a5, a6, a7);
        accum_tap(p01, w01, a0, a1, a2, a3, a4, a5, a6, a7);
        accum_tap(p11, w11, a0, a1, a2, a3, a4, a5, a6, a7);

        rx += fx;
        ry += fy;
    }

    float* o = out + (size_t)t * C_ * HW_ + hw;
    o[0 * HW_] = a0;
    o[1 * HW_] = a1;
    o[2 * HW_] = a2;
    o[3 * HW_] = a3;
    o[4 * HW_] = a4;
    o[5 * HW_] = a5;
    o[6 * HW_] = a6;
    o[7 * HW_] = a7;
}

// ---------------------------------------------------------------------------
extern "C" void kernel_launch(void* const* d_in, const int* in_sizes, int n_in,
                              void* d_out, int out_size) {
    const float* flows  = (const float*)d_in[0];   // [1,16,2,128,128]
    const float* images = (const float*)d_in[1];   // [1,16,8,128,128]
    float* out = (float*)d_out;                    // [1,16,8,128,128]

    (void)in_sizes; (void)n_in; (void)out_size;

    {
        int total = L_ * HW_;
        int threads = 256;
        int blocks = (total + threads - 1) / threads;
        transpose_nhwc_kernel<<<blocks, threads>>>(images);
    }
    {
        dim3 grid(H_, L_);
        dim3 block(W_);
        pscan_sample_kernel<<<grid, block>>>(flows, out);
    }
}